// round 6
// baseline (speedup 1.0000x reference)
#include <cuda_runtime.h>
#include <math.h>

// Problem constants
#define NB   2
#define NS   128
#define NROW (NB*NS)        // 256 rows (b*s)
#define NN   512            // feature dim
#define NM   1024           // 2*N output cols of GEMM
#define NK   512            // contraction dim

#define SAMPLE_ELEMS (NROW*NN)               // 131072
#define STD_ELEMS    ((long long)NROW*NN*NN) // 67108864
#define STD4         (STD_ELEMS >> 2)        // 16777216 float4

#define GBM 32
#define GBN 64
#define GBK 32
#define KS  4
#define KPER (NK/KS)        // 128
#define KITERS (KPER/GBK)   // 4

#define GEMM_CTAS 512                 // 16 x 8 x 4
#define F_STRIDE  (GEMM_CTAS * 256)   // 131072 threads total
#define F_PER_TH  128                 // 131072 * 128 = 16777216 float4  (exact)
#define F_CHUNK   32                  // 4 weave slots x 32 stores

// Scratch (no allocations allowed)
__device__ float g_part[KS * NROW * NM];   // 4 MB split-K partials

// ---------------- Fused kernel: every CTA = GEMM tile + zero-fill weave -----
__global__ __launch_bounds__(256)
void fused_kernel(const float* __restrict__ A, const float* __restrict__ W,
                  float* __restrict__ P, float4* __restrict__ out4) {
    __shared__ __align__(16) float As[2][GBK][GBM + 2];
    __shared__ __align__(16) float Bs[2][GBK][GBN + 4];

    const int bid = blockIdx.x;
    const int tid = threadIdx.x;

    const int bx = bid & 15;          // N tile (0..15)
    const int by = (bid >> 4) & 7;    // M tile (0..7)
    const int bz = bid >> 7;          // K split (0..3)

    const int ty = tid >> 4;          // 0..15 -> rows ty*2, ty*2+1
    const int tx = tid & 15;          // cols tx*4 .. tx*4+3

    const int lr = tid >> 3;          // 0..31
    const int lk = (tid & 7) << 2;    // 0,4,...,28

    const float* Ag  = A + (size_t)(by * GBM + lr) * NK + bz * KPER;
    const float* Wg0 = W + (size_t)(bx * GBN + lr) * NK + bz * KPER;
    const float* Wg1 = Wg0 + (size_t)32 * NK;

    // Fill-weave state: thread covers idx = fbase + k*F_STRIDE, k = 0..127
    const float4 zz = make_float4(0.f, 0.f, 0.f, 0.f);
    long long fidx = (long long)bid * 256 + tid;

    float acc[2][4] = {};

    // Prologue: tile 0 -> buffer 0
    float4 a4 = *(const float4*)(Ag  + lk);
    float4 b0 = *(const float4*)(Wg0 + lk);
    float4 b1 = *(const float4*)(Wg1 + lk);
    #pragma unroll
    for (int q = 0; q < 4; q++) {
        As[0][lk + q][lr]      = ((const float*)&a4)[q];
        Bs[0][lk + q][lr]      = ((const float*)&b0)[q];
        Bs[0][lk + q][lr + 32] = ((const float*)&b1)[q];
    }
    __syncthreads();

    int buf = 0;
    for (int it = 0; it < KITERS; it++) {
        float4 na, nb0, nb1;
        const bool more = (it + 1 < KITERS);
        if (more) {
            na  = *(const float4*)(Ag  + (it + 1) * GBK + lk);
            nb0 = *(const float4*)(Wg0 + (it + 1) * GBK + lk);
            nb1 = *(const float4*)(Wg1 + (it + 1) * GBK + lk);
        }

        #pragma unroll
        for (int kk = 0; kk < GBK; kk++) {
            float2 a2 = *(const float2*)&As[buf][kk][ty * 2];
            float4 w4 = *(const float4*)&Bs[buf][kk][tx * 4];
            acc[0][0] = fmaf(a2.x, w4.x, acc[0][0]);
            acc[0][1] = fmaf(a2.x, w4.y, acc[0][1]);
            acc[0][2] = fmaf(a2.x, w4.z, acc[0][2]);
            acc[0][3] = fmaf(a2.x, w4.w, acc[0][3]);
            acc[1][0] = fmaf(a2.y, w4.x, acc[1][0]);
            acc[1][1] = fmaf(a2.y, w4.y, acc[1][1]);
            acc[1][2] = fmaf(a2.y, w4.z, acc[1][2]);
            acc[1][3] = fmaf(a2.y, w4.w, acc[1][3]);
        }

        // Weave: post 32 streaming zero-stores (fire-and-forget, LSU pipe)
        #pragma unroll
        for (int q = 0; q < F_CHUNK; q++) {
            __stcs(&out4[fidx], zz);
            fidx += F_STRIDE;
        }

        if (more) {
            const int nb = buf ^ 1;
            #pragma unroll
            for (int q = 0; q < 4; q++) {
                As[nb][lk + q][lr]      = ((const float*)&na)[q];
                Bs[nb][lk + q][lr]      = ((const float*)&nb0)[q];
                Bs[nb][lk + q][lr + 32] = ((const float*)&nb1)[q];
            }
            __syncthreads();
            buf = nb;
        }
    }

    // Epilogue: write split-K partial
    float* Pp = P + (size_t)bz * (NROW * NM);
    #pragma unroll
    for (int i = 0; i < 2; i++) {
        const int row = by * GBM + ty * 2 + i;
        float4 v = make_float4(acc[i][0], acc[i][1], acc[i][2], acc[i][3]);
        *(float4*)(Pp + (size_t)row * NM + bx * GBN + tx * 4) = v;
    }
}

// ---------------- Pointwise: reduce split-K + var/mu/sample + diagonal ------
__device__ __forceinline__ float softplus_f(float x) {
    return fmaxf(x, 0.0f) + log1pf(expf(-fabsf(x)));
}

__global__ __launch_bounds__(256)
void pointwise_kernel(const float* __restrict__ P,
                      const float* __restrict__ bias,
                      const float* __restrict__ eps,
                      float4* __restrict__ out_sample,
                      float4* __restrict__ out_mu,
                      float* __restrict__ out_std) {
    int t = blockIdx.x * blockDim.x + threadIdx.x;   // 0 .. 32767 (float4 units)
    if (t >= SAMPLE_ELEMS / 4) return;
    int row = t >> 7;                 // /128 float4-per-row
    int i4  = (t & 127);              // float4 col index
    int i   = i4 << 2;                // float col

    float4 sv = ((const float4*)bias)[i4];                 // bias[i..i+3]
    float4 sm = ((const float4*)bias)[(NN >> 2) + i4];     // bias[NN+i..]
    #pragma unroll
    for (int z = 0; z < KS; z++) {
        const float4* Pz = (const float4*)(P + (size_t)z * (NROW * NM) + (size_t)row * NM);
        float4 pv = Pz[i4];
        float4 pm = Pz[(NN >> 2) + i4];
        sv.x += pv.x; sv.y += pv.y; sv.z += pv.z; sv.w += pv.w;
        sm.x += pm.x; sm.y += pm.y; sm.z += pm.z; sm.w += pm.w;
    }

    float4 var;
    var.x = softplus_f(sv.x); var.y = softplus_f(sv.y);
    var.z = softplus_f(sv.z); var.w = softplus_f(sv.w);

    float4 ep = ((const float4*)eps)[t];
    float4 smp;
    smp.x = fmaf(sqrtf(var.x), ep.x, sm.x);
    smp.y = fmaf(sqrtf(var.y), ep.y, sm.y);
    smp.z = fmaf(sqrtf(var.z), ep.z, sm.z);
    smp.w = fmaf(sqrtf(var.w), ep.w, sm.w);

    out_mu[t]     = sm;
    out_sample[t] = smp;

    // Diagonal scatter: sample index idx = row*NN + i + q, diag col = i + q
    const size_t base = ((size_t)row * NN + i) * NN + i;   // (idx)*NN + col
    out_std[base]              = var.x;   // q=0
    out_std[base + NN + 1]     = var.y;   // q=1: +NN rows, +1 col
    out_std[base + 2*(NN + 1)] = var.z;
    out_std[base + 3*(NN + 1)] = var.w;
}

extern "C" void kernel_launch(void* const* d_in, const int* in_sizes, int n_in,
                              void* d_out, int out_size) {
    const float* x   = (const float*)d_in[0];
    const float* W   = (const float*)d_in[1];
    const float* b   = (const float*)d_in[2];
    const float* eps = (const float*)d_in[3];

    float* out        = (float*)d_out;
    float* out_sample = out;
    float* out_mu     = out + SAMPLE_ELEMS;
    float* out_std    = out + 2 * SAMPLE_ELEMS;

    float* part;  cudaGetSymbolAddress((void**)&part, g_part);

    // 1) Fused: 512 CTAs, each = one split-K GEMM tile + 1/512 of the zero fill
    fused_kernel<<<GEMM_CTAS, 256>>>(x, W, part, (float4*)out_std);

    // 2) pointwise: split-K reduce + sample/mu + diagonal scatter (vectorized)
    pointwise_kernel<<<(SAMPLE_ELEMS / 4) / 256, 256>>>(part, b, eps,
                                                        (float4*)out_sample,
                                                        (float4*)out_mu, out_std);
}

// round 7
// speedup vs baseline: 1.0110x; 1.0110x over previous
#include <cuda_runtime.h>
#include <math.h>

// Problem constants
#define NB   2
#define NS   128
#define NROW (NB*NS)        // 256 rows (b*s)
#define NN   512            // feature dim
#define NM   1024           // 2*N output cols of GEMM
#define NK   512            // contraction dim

#define SAMPLE_ELEMS (NROW*NN)               // 131072
#define STD_ELEMS    ((long long)NROW*NN*NN) // 67108864

// GEMM tiling: 64x64x16, split-K=4 -> 16(N) x 4(M) x 4(K) = 256 CTAs
#define BM 64
#define BN 64
#define BK 16
#define KS 4
#define KPER (NK/KS)        // 128
#define KIT  (KPER/BK)      // 8

// Scratch (no allocations allowed)
__device__ float g_part[KS * NROW * NM];   // 4 MB split-K partials

// ---------------- Split-K GEMM: 4x4 micro-tile, double-buffered -------------
__global__ __launch_bounds__(256)
void gemm_kernel(const float* __restrict__ A, const float* __restrict__ W,
                 float* __restrict__ P) {
    __shared__ __align__(16) float As[2][BK][BM + 4];
    __shared__ __align__(16) float Bs[2][BK][BN + 4];

    const int tid = threadIdx.x;
    const int bx = blockIdx.x & 15;         // N tile (0..15)
    const int by = (blockIdx.x >> 4) & 3;   // M tile (0..3)
    const int bz = blockIdx.x >> 6;         // K split (0..3)

    const int ty = tid >> 4;                // 0..15 -> rows ty*4..+3
    const int tx = tid & 15;                // cols tx*4..+3
    const int m0 = ty * 4;
    const int n0 = tx * 4;

    const int lrow = tid >> 2;              // 0..63
    const int lk4  = (tid & 3) << 2;        // 0,4,8,12

    const float* Ag = A + (size_t)(by * BM + lrow) * NK + bz * KPER;
    const float* Wg = W + (size_t)(bx * BN + lrow) * NK + bz * KPER;

    float acc[4][4] = {};

    // Prologue: tile 0 -> buffer 0
    float4 a4 = *(const float4*)(Ag + lk4);
    float4 w4 = *(const float4*)(Wg + lk4);
    #pragma unroll
    for (int q = 0; q < 4; q++) {
        As[0][lk4 + q][lrow] = ((const float*)&a4)[q];
        Bs[0][lk4 + q][lrow] = ((const float*)&w4)[q];
    }
    __syncthreads();

    int buf = 0;
    for (int it = 0; it < KIT; it++) {
        float4 na, nw;
        const bool more = (it + 1 < KIT);
        if (more) {
            na = *(const float4*)(Ag + (it + 1) * BK + lk4);
            nw = *(const float4*)(Wg + (it + 1) * BK + lk4);
        }

        #pragma unroll
        for (int kk = 0; kk < BK; kk++) {
            float4 av = *(const float4*)&As[buf][kk][m0];
            float4 wv = *(const float4*)&Bs[buf][kk][n0];
            #pragma unroll
            for (int i = 0; i < 4; i++) {
                float ai = ((const float*)&av)[i];
                acc[i][0] = fmaf(ai, wv.x, acc[i][0]);
                acc[i][1] = fmaf(ai, wv.y, acc[i][1]);
                acc[i][2] = fmaf(ai, wv.z, acc[i][2]);
                acc[i][3] = fmaf(ai, wv.w, acc[i][3]);
            }
        }

        if (more) {
            const int nb = buf ^ 1;
            #pragma unroll
            for (int q = 0; q < 4; q++) {
                As[nb][lk4 + q][lrow] = ((const float*)&na)[q];
                Bs[nb][lk4 + q][lrow] = ((const float*)&nw)[q];
            }
            __syncthreads();
            buf = nb;
        }
    }

    // Epilogue: write split-K partials (float4 per row)
    float* Pp = P + (size_t)bz * (NROW * NM);
    #pragma unroll
    for (int i = 0; i < 4; i++) {
        const int row = by * BM + m0 + i;
        float4 v = make_float4(acc[i][0], acc[i][1], acc[i][2], acc[i][3]);
        *(float4*)(Pp + (size_t)row * NM + bx * BN + n0) = v;
    }
}

// ---------------- Fill std_mat: pure zeros (branchless stream) --------------
__global__ __launch_bounds__(256)
void fill_std_kernel(float4* __restrict__ out4) {
    const long long total4 = STD_ELEMS >> 2;   // 16777216 float4
    long long idx = (long long)blockIdx.x * blockDim.x + threadIdx.x;
    const long long stride = (long long)gridDim.x * blockDim.x;
    const float4 z = make_float4(0.f, 0.f, 0.f, 0.f);
    for (; idx < total4; idx += stride)
        __stcs(&out4[idx], z);
}

// ---------------- Pointwise: reduce split-K + var/mu/sample + diagonal ------
__device__ __forceinline__ float softplus_f(float x) {
    return fmaxf(x, 0.0f) + log1pf(expf(-fabsf(x)));
}

__global__ __launch_bounds__(256)
void pointwise_kernel(const float* __restrict__ P,
                      const float* __restrict__ bias,
                      const float* __restrict__ eps,
                      float* __restrict__ out_sample,
                      float* __restrict__ out_mu,
                      float* __restrict__ out_std) {
    int idx = blockIdx.x * blockDim.x + threadIdx.x;
    if (idx >= SAMPLE_ELEMS) return;
    int row = idx >> 9;          // /512
    int i   = idx & (NN - 1);

    float s_var = bias[i];
    float s_mu  = bias[NN + i];
    #pragma unroll
    for (int z = 0; z < KS; z++) {
        const float* Pz = P + (size_t)z * (NROW * NM) + (size_t)row * NM;
        s_var += Pz[i];
        s_mu  += Pz[NN + i];
    }
    float var = softplus_f(s_var);
    out_mu[idx]     = s_mu;
    out_sample[idx] = fmaf(sqrtf(var), eps[idx], s_mu);
    // Diagonal scatter (fill ran before us; zeros already laid down)
    out_std[(size_t)idx * NN + i] = var;
}

extern "C" void kernel_launch(void* const* d_in, const int* in_sizes, int n_in,
                              void* d_out, int out_size) {
    const float* x   = (const float*)d_in[0];
    const float* W   = (const float*)d_in[1];
    const float* b   = (const float*)d_in[2];
    const float* eps = (const float*)d_in[3];

    float* out        = (float*)d_out;
    float* out_sample = out;
    float* out_mu     = out + SAMPLE_ELEMS;
    float* out_std    = out + 2 * SAMPLE_ELEMS;

    float* part;  cudaGetSymbolAddress((void**)&part, g_part);

    // 1) Split-K GEMM -> partials (256 CTAs, 4x4 micro-tile)
    gemm_kernel<<<16 * 4 * KS, 256>>>(x, W, part);

    // 2) Zero-fill std_mat (256 MB, DRAM-roofline stream)
    fill_std_kernel<<<8192, 256>>>((float4*)out_std);

    // 3) Pointwise: split-K reduce + sample/mu + diagonal scatter
    pointwise_kernel<<<SAMPLE_ELEMS / 256, 256>>>(part, b, eps,
                                                  out_sample, out_mu, out_std);
}